// round 15
// baseline (speedup 1.0000x reference)
#include <cuda_runtime.h>
#include <cuda_bf16.h>
#include <math.h>

#define NN      20000
#define NE      320000
#define INDIM   128
#define HID     256
#define HEADS   8
#define DH      32
#define LAYERS  3
#define NG      64
#define OUTDIM  10
#define SLOPE   0.2f

#define K2IN  (INDIM / 2)
#define K2L   (HID / 2)
#define WIN_P (K2IN * HID)
#define WL_P  (K2L * HID)

// ---------------- scratch (device globals; no allocation allowed) ----------
__device__ float g_h[NN * HID];
__device__ float g_fs[NN * HID];
__device__ float g_fd[NN * HID];
__device__ unsigned g_ah_hi[NN * K2L];
__device__ unsigned g_ah_lo[NN * K2L];
__device__ unsigned g_af_hi[NN * K2IN];
__device__ unsigned g_af_lo[NN * K2IN];
__device__ unsigned g_win_hi[WIN_P], g_win_lo[WIN_P];
__device__ unsigned g_ws_hi[LAYERS * WL_P], g_ws_lo[LAYERS * WL_P];
__device__ unsigned g_wd_hi[LAYERS * WL_P], g_wd_lo[LAYERS * WL_P];
__device__ int g_cnt[NN];
__device__ int g_base[NN + 1];
__device__ int g_cur[NN];
__device__ int g_srcbyd[NE];
__device__ int g_gstart[NG + 1];

// ---------------- bf16 pack helpers -----------------------------------------
__device__ __forceinline__ unsigned pack_bf2(__nv_bfloat16 a, __nv_bfloat16 b) {
    return ((unsigned)__bfloat16_as_ushort(b) << 16) | (unsigned)__bfloat16_as_ushort(a);
}

__device__ __forceinline__ void split_pack(float x0, float x1, unsigned& hi, unsigned& lo) {
    __nv_bfloat16 h0 = __float2bfloat16_rn(x0);
    __nv_bfloat16 h1 = __float2bfloat16_rn(x1);
    __nv_bfloat16 l0 = __float2bfloat16_rn(x0 - __bfloat162float(h0));
    __nv_bfloat16 l1 = __float2bfloat16_rn(x1 - __bfloat162float(h1));
    hi = pack_bf2(h0, h1);
    lo = pack_bf2(l0, l1);
}

__device__ __forceinline__ void mma_bf16(float c[4], const unsigned a[4], const unsigned b[2]) {
    asm volatile(
        "mma.sync.aligned.m16n8k16.row.col.f32.bf16.bf16.f32 "
        "{%0,%1,%2,%3}, {%4,%5,%6,%7}, {%8,%9}, {%0,%1,%2,%3};"
        : "+f"(c[0]), "+f"(c[1]), "+f"(c[2]), "+f"(c[3])
        : "r"(a[0]), "r"(a[1]), "r"(a[2]), "r"(a[3]), "r"(b[0]), "r"(b[1]));
}

__device__ __forceinline__ void ldsm_x4(unsigned r[4], unsigned addr) {
    asm volatile("ldmatrix.sync.aligned.m8n8.x4.shared.b16 {%0,%1,%2,%3}, [%4];"
        : "=r"(r[0]), "=r"(r[1]), "=r"(r[2]), "=r"(r[3]) : "r"(addr));
}

__device__ __forceinline__ void cp_async16(unsigned saddr, const void* g, unsigned srcsz) {
    asm volatile("cp.async.cg.shared.global [%0], [%1], 16, %2;"
                 :: "r"(saddr), "l"(g), "r"(srcsz) : "memory");
}
#define CP_COMMIT() asm volatile("cp.async.commit_group;" ::: "memory")
#define CP_WAIT(n)  asm volatile("cp.async.wait_group %0;" :: "n"(n) : "memory")

// ---------------- pack: feature + W_in (main stream, feeds GEMM1) -------------
__global__ void pack_in_kernel(const float* __restrict__ W_in,
                               const float* __restrict__ feature)
{
    int i = blockIdx.x * blockDim.x + threadIdx.x;
    const int NF = NN * K2IN;
    if (i < NF) {
        float2 v = ((const float2*)feature)[i];
        split_pack(v.x, v.y, g_af_hi[i], g_af_lo[i]);
        return;
    }
    int j = i - NF;
    if (j >= WIN_P) return;
    int k2 = j >> 8, n = j & 255;
    split_pack(W_in[(2 * k2) * HID + n], W_in[(2 * k2 + 1) * HID + n],
               g_win_hi[j], g_win_lo[j]);
}

// ---------------- pack: layer weights (stream 2, overlapped) ------------------
__global__ void pack_lw_kernel(const float* __restrict__ W_src,
                               const float* __restrict__ W_dst)
{
    int j = blockIdx.x * blockDim.x + threadIdx.x;
    if (j >= 2 * LAYERS * WL_P) return;
    int which = j / (LAYERS * WL_P);
    int rem = j - which * (LAYERS * WL_P);
    int l = rem / WL_P;
    int p = rem - l * WL_P;
    int k2 = p >> 8, n = p & 255;
    const float* W = (which ? W_dst : W_src) + (size_t)l * HID * HID;
    unsigned* hi = (which ? g_wd_hi : g_ws_hi) + (size_t)l * WL_P;
    unsigned* lo = (which ? g_wd_lo : g_ws_lo) + (size_t)l * WL_P;
    split_pack(W[(2 * k2) * HID + n], W[(2 * k2 + 1) * HID + n], hi[p], lo[p]);
}

// ------- bf16x3 mma.sync GEMM: 64x128 tile, cp.async 3-stage pipeline --------
#define GBM 64
#define GBN 128
#define AST 20
#define BST 136
#define STG   27648
#define GSMEM (3 * STG)           // 82944 -> 2 CTAs/SM

__global__ __launch_bounds__(256) void gemm_bf16x3_kernel(
    const unsigned* __restrict__ Ahi, const unsigned* __restrict__ Alo,
    const unsigned* __restrict__ B1hi, const unsigned* __restrict__ B1lo,
    const unsigned* __restrict__ B2hi, const unsigned* __restrict__ B2lo,
    const float* __restrict__ bias1, const float* __restrict__ bias2,
    float* __restrict__ C1, float* __restrict__ C2,
    unsigned* __restrict__ Pho, unsigned* __restrict__ Plo,
    int M, int K2g, int nb, int do_pack)
{
    extern __shared__ __align__(16) unsigned char dsm[];
    const unsigned sbase = (unsigned)__cvta_generic_to_shared(dsm);

    int bx = blockIdx.x;
    int which = 0;
    if (bx >= nb) { which = 1; bx -= nb; }
    const unsigned* Bhi = which ? B2hi : B1hi;
    const unsigned* Blo = which ? B2lo : B1lo;
    const float* bias   = which ? bias2 : bias1;
    float* C            = which ? C2 : C1;

    const int tid  = threadIdx.x;
    const int wid  = tid >> 5;
    const int lane = tid & 31;
    const int wm   = (wid >> 2) * 32;
    const int wn   = (wid & 3) * 32;
    const int grp  = lane >> 2;
    const int tig  = lane & 3;
    const int row0 = blockIdx.y * GBM;
    const int col0 = bx * GBN;

    const int arw = tid >> 2;
    const int asg = (tid & 3) * 4;
    const int brw = tid >> 5;
    const int bcc = (tid & 31) * 4;

    const int lrow = wm + (lane & 15);
    const int lcol = (lane >> 4) * 4;

    const bool a_ok = (row0 + arw) < M;
    const int arow_c = a_ok ? (row0 + arw) : (M - 1);
    const unsigned a_srcsz = a_ok ? 16u : 0u;
    const unsigned a_soff = (arw * AST + asg) * 4u;
    const unsigned b_soff0 = 10240u + (brw * BST + bcc) * 4u;
    const unsigned b_soff1 = 10240u + ((brw + 8) * BST + bcc) * 4u;

    #define ISSUE_TILE(t, s) do {                                             \
        int kb = (t) * 16;                                                    \
        unsigned sb = sbase + (unsigned)(s) * STG;                            \
        size_t ga = (size_t)arow_c * K2g + kb + asg;                          \
        cp_async16(sb + a_soff,         Ahi + ga, a_srcsz);                   \
        cp_async16(sb + 5120 + a_soff,  Alo + ga, a_srcsz);                   \
        size_t gb0 = (size_t)(kb + brw) * 256 + col0 + bcc;                   \
        size_t gb1 = (size_t)(kb + brw + 8) * 256 + col0 + bcc;               \
        cp_async16(sb + b_soff0,        Bhi + gb0, 16u);                      \
        cp_async16(sb + 8704 + b_soff0, Blo + gb0, 16u);                      \
        cp_async16(sb + b_soff1,        Bhi + gb1, 16u);                      \
        cp_async16(sb + 8704 + b_soff1, Blo + gb1, 16u);                      \
    } while (0)

    float c[2][4][4];
    #pragma unroll
    for (int i = 0; i < 2; i++)
        #pragma unroll
        for (int j = 0; j < 4; j++)
            #pragma unroll
            for (int k = 0; k < 4; k++) c[i][j][k] = 0.f;

    const int nk = K2g >> 4;
    ISSUE_TILE(0, 0);
    CP_COMMIT();
    if (nk > 1) { ISSUE_TILE(1, 1); CP_COMMIT(); }

    int s = 0;
    for (int t = 0; t < nk; t++) {
        if (t + 1 < nk) CP_WAIT(1); else CP_WAIT(0);
        __syncthreads();

        const unsigned stg = sbase + (unsigned)s * STG;
        const unsigned* Bsh = (const unsigned*)(dsm + s * STG + 10240);
        const unsigned* Bsl = (const unsigned*)(dsm + s * STG + 18944);

        #pragma unroll
        for (int kk = 0; kk < 2; kk++) {
            unsigned ah[2][4], al[2][4], bh[4][2], bl[4][2];
            #pragma unroll
            for (int mt = 0; mt < 2; mt++) {
                unsigned off = ((unsigned)(lrow + mt * 16) * AST + kk * 8 + lcol) * 4u;
                ldsm_x4(ah[mt], stg + off);
                ldsm_x4(al[mt], stg + 5120 + off);
            }
            #pragma unroll
            for (int nt = 0; nt < 4; nt++) {
                int cn = wn + nt * 8 + grp;
                int r0 = (kk * 8 + tig) * BST;
                bh[nt][0] = Bsh[r0 + cn];      bh[nt][1] = Bsh[r0 + 4 * BST + cn];
                bl[nt][0] = Bsl[r0 + cn];      bl[nt][1] = Bsl[r0 + 4 * BST + cn];
            }
            #pragma unroll
            for (int mt = 0; mt < 2; mt++)
                #pragma unroll
                for (int nt = 0; nt < 4; nt++) {
                    mma_bf16(c[mt][nt], ah[mt], bl[nt]);
                    mma_bf16(c[mt][nt], al[mt], bh[nt]);
                    mma_bf16(c[mt][nt], ah[mt], bh[nt]);
                }
        }

        if (t + 2 < nk) {
            int s2i = s + 2; if (s2i >= 3) s2i -= 3;
            ISSUE_TILE(t + 2, s2i);
            CP_COMMIT();
        }
        s = (s + 1 == 3) ? 0 : s + 1;
    }

    #pragma unroll
    for (int nt = 0; nt < 4; nt++) {
        int cc = col0 + wn + nt * 8 + 2 * tig;
        float b0 = bias[cc], b1 = bias[cc + 1];
        #pragma unroll
        for (int mt = 0; mt < 2; mt++) {
            int r0 = row0 + wm + mt * 16 + grp;
            if (r0 < M) {
                float v0 = c[mt][nt][0] + b0, v1 = c[mt][nt][1] + b1;
                *(float2*)(C + (size_t)r0 * HID + cc) = make_float2(v0, v1);
                if (do_pack && which == 0) {
                    unsigned hi, lo;
                    split_pack(v0, v1, hi, lo);
                    size_t pi = ((size_t)r0 * HID + cc) >> 1;
                    Pho[pi] = hi; Plo[pi] = lo;
                }
            }
            int r1 = r0 + 8;
            if (r1 < M) {
                float v0 = c[mt][nt][2] + b0, v1 = c[mt][nt][3] + b1;
                *(float2*)(C + (size_t)r1 * HID + cc) = make_float2(v0, v1);
                if (do_pack && which == 0) {
                    unsigned hi, lo;
                    split_pack(v0, v1, hi, lo);
                    size_t pi = ((size_t)r1 * HID + cc) >> 1;
                    Pho[pi] = hi; Plo[pi] = lo;
                }
            }
        }
    }
    #undef ISSUE_TILE
}

// ---------------- CSR build (second stream) ----------------------------------
__global__ void zero_cnt_kernel() {
    int i = blockIdx.x * blockDim.x + threadIdx.x;
    if (i < NN) g_cnt[i] = 0;
}

__global__ void count_kernel(const int* __restrict__ dst) {
    int e = blockIdx.x * blockDim.x + threadIdx.x;
    if (e < NE) atomicAdd(&g_cnt[dst[e]], 1);
}

__global__ __launch_bounds__(1024) void scan_kernel() {
    __shared__ int s[1024];
    int t = threadIdx.x;
    int lo = t * 20;
    int hi = lo + 20; if (hi > NN) hi = NN;
    int sum = 0;
    for (int i = lo; i < hi; i++) sum += g_cnt[i];
    s[t] = sum;
    __syncthreads();
    for (int off = 1; off < 1024; off <<= 1) {
        int v = (t >= off) ? s[t - off] : 0;
        __syncthreads();
        s[t] += v;
        __syncthreads();
    }
    int run = s[t] - sum;
    for (int i = lo; i < hi; i++) {
        g_base[i] = run;
        g_cur[i] = run;
        run += g_cnt[i];
    }
    if (t == 0) g_base[NN] = NE;
}

__global__ void fill_kernel(const int* __restrict__ src, const int* __restrict__ dst) {
    int e = blockIdx.x * blockDim.x + threadIdx.x;
    if (e < NE) {
        int p = atomicAdd(&g_cur[dst[e]], 1);
        g_srcbyd[p] = src[e];
    }
}

__global__ void gbound_kernel(const int* __restrict__ gids) {
    int g = threadIdx.x;
    if (g > NG) return;
    int lo = 0, hi = NN;
    while (lo < hi) {
        int mid = (lo + hi) >> 1;
        if (gids[mid] < g) lo = mid + 1; else hi = mid;
    }
    g_gstart[g] = lo;
}

// ------- fused edge kernel: warp per node, unroll-by-4 (MLP=8) ---------------
__device__ __forceinline__ void edge_update(float fsv[8], float p,
                                            float& m, float& sd, float acc[8])
{
    float nm = fmaxf(m, p);
    float fac = __expf(m - nm);
    float w   = __expf(p - nm);
    sd = sd * fac + w;
    #pragma unroll
    for (int q = 0; q < 8; q++) acc[q] = fmaf(acc[q], fac, w * fsv[q]);
    m = nm;
}

__global__ __launch_bounds__(256) void fused_edge_kernel(const float* __restrict__ attn,
                                                         int do_pack)
{
    int n = blockIdx.x * 8 + (threadIdx.x >> 5);
    int lane = threadIdx.x & 31;
    if (n >= NN) return;
    const size_t rowoff = (size_t)n * HID + lane * 8;

    float fdv[8], av[8];
    {
        float4 t0 = *(const float4*)(g_fd + rowoff);
        float4 t1 = *(const float4*)(g_fd + rowoff + 4);
        fdv[0]=t0.x; fdv[1]=t0.y; fdv[2]=t0.z; fdv[3]=t0.w;
        fdv[4]=t1.x; fdv[5]=t1.y; fdv[6]=t1.z; fdv[7]=t1.w;
        float4 a0 = *(const float4*)(attn + lane * 8);
        float4 a1 = *(const float4*)(attn + lane * 8 + 4);
        av[0]=a0.x; av[1]=a0.y; av[2]=a0.z; av[3]=a0.w;
        av[4]=a1.x; av[5]=a1.y; av[6]=a1.z; av[7]=a1.w;
    }

    const int b  = __ldg(&g_base[n]);
    const int e2 = __ldg(&g_base[n + 1]);

    float m = -1e30f, sd = 0.f;
    float acc[8] = {0.f,0.f,0.f,0.f,0.f,0.f,0.f,0.f};

    int j = b;
    for (; j + 4 <= e2; j += 4) {
        int sI[4];
        #pragma unroll
        for (int u = 0; u < 4; u++) sI[u] = __ldg(&g_srcbyd[j + u]);
        float4 lo4[4], hi4[4];
        #pragma unroll
        for (int u = 0; u < 4; u++) {
            const float4* f = (const float4*)(g_fs + (size_t)sI[u] * HID + lane * 8);
            lo4[u] = f[0];
            hi4[u] = f[1];
        }
        float fsv[4][8];
        float p[4];
        #pragma unroll
        for (int u = 0; u < 4; u++) {
            fsv[u][0]=lo4[u].x; fsv[u][1]=lo4[u].y; fsv[u][2]=lo4[u].z; fsv[u][3]=lo4[u].w;
            fsv[u][4]=hi4[u].x; fsv[u][5]=hi4[u].y; fsv[u][6]=hi4[u].z; fsv[u][7]=hi4[u].w;
            float pp = 0.f;
            #pragma unroll
            for (int q = 0; q < 8; q++) {
                float v = fsv[u][q] + fdv[q];
                v = (v > 0.f) ? v : SLOPE * v;
                pp = fmaf(v, av[q], pp);
            }
            p[u] = pp;
        }
        #pragma unroll
        for (int u = 0; u < 4; u++) {
            p[u] += __shfl_xor_sync(0xffffffffu, p[u], 1);
            p[u] += __shfl_xor_sync(0xffffffffu, p[u], 2);
        }
        #pragma unroll
        for (int u = 0; u < 4; u++)
            edge_update(fsv[u], p[u], m, sd, acc);
    }
    for (; j < e2; j++) {
        int s0 = __ldg(&g_srcbyd[j]);
        const float4* f0 = (const float4*)(g_fs + (size_t)s0 * HID + lane * 8);
        float4 a00 = f0[0], a01 = f0[1];
        float fsv0[8] = {a00.x,a00.y,a00.z,a00.w,a01.x,a01.y,a01.z,a01.w};
        float p0 = 0.f;
        #pragma unroll
        for (int q = 0; q < 8; q++) {
            float v0 = fsv0[q] + fdv[q];
            v0 = (v0 > 0.f) ? v0 : SLOPE * v0;
            p0 = fmaf(v0, av[q], p0);
        }
        p0 += __shfl_xor_sync(0xffffffffu, p0, 1);
        p0 += __shfl_xor_sync(0xffffffffu, p0, 2);
        edge_update(fsv0, p0, m, sd, acc);
    }

    float inv = (sd > 0.f) ? 1.f / sd : 0.f;
    float hv[8];
    {
        float4 h0 = *(const float4*)(g_h + rowoff);
        float4 h1 = *(const float4*)(g_h + rowoff + 4);
        float hold[8] = {h0.x,h0.y,h0.z,h0.w,h1.x,h1.y,h1.z,h1.w};
        #pragma unroll
        for (int q = 0; q < 8; q++) hv[q] = fmaxf(fmaf(acc[q], inv, hold[q]), 0.f);
    }
    *(float4*)(g_h + rowoff)     = make_float4(hv[0], hv[1], hv[2], hv[3]);
    *(float4*)(g_h + rowoff + 4) = make_float4(hv[4], hv[5], hv[6], hv[7]);
    if (do_pack) {
        size_t pbase = rowoff >> 1;
        #pragma unroll
        for (int q = 0; q < 8; q += 2) {
            unsigned hi, lo;
            split_pack(hv[q], hv[q + 1], hi, lo);
            g_ah_hi[pbase + (q >> 1)] = hi;
            g_ah_lo[pbase + (q >> 1)] = lo;
        }
    }
}

// ---------------- fused pool + 3-layer classifier, one block per graph -------
__global__ __launch_bounds__(256) void poolfc_kernel(
    const float* __restrict__ Wc1, const float* __restrict__ bc1,
    const float* __restrict__ Wc2, const float* __restrict__ bc2,
    const float* __restrict__ Wc3, const float* __restrict__ bc3,
    float* __restrict__ out)
{
    __shared__ float sh[256];
    __shared__ float sx[256];
    int g = blockIdx.x;
    int c = threadIdx.x;
    int n0 = g_gstart[g], n1 = g_gstart[g + 1];
    float s = 0.f;
    for (int n = n0; n < n1; n++) s += g_h[(size_t)n * HID + c];
    sh[c] = s;
    __syncthreads();
    float a = bc1[c];
    #pragma unroll 8
    for (int k = 0; k < HID; k++) a = fmaf(sh[k], Wc1[k * HID + c], a);
    sx[c] = fmaxf(a, 0.f);
    __syncthreads();
    float b2 = 0.f;
    if (c < HID / 2) {
        b2 = bc2[c];
        #pragma unroll 8
        for (int k = 0; k < HID; k++) b2 = fmaf(sx[k], Wc2[k * (HID / 2) + c], b2);
        b2 = fmaxf(b2, 0.f);
    }
    __syncthreads();
    if (c < HID / 2) sh[c] = b2;
    __syncthreads();
    if (c < OUTDIM) {
        float o = bc3[c];
        for (int k = 0; k < HID / 2; k++) o = fmaf(sh[k], Wc3[k * OUTDIM + c], o);
        out[g * OUTDIM + c] = o;
    }
}

// ---------------- launch -------------------------------------------------------
extern "C" void kernel_launch(void* const* d_in, const int* in_sizes, int n_in,
                              void* d_out, int out_size)
{
    const float* feature   = (const float*)d_in[0];
    const float* W_in      = (const float*)d_in[1];
    const float* b_in      = (const float*)d_in[2];
    const float* W_src     = (const float*)d_in[3];
    const float* b_src     = (const float*)d_in[4];
    const float* W_dst     = (const float*)d_in[5];
    const float* b_dst     = (const float*)d_in[6];
    const float* attn      = (const float*)d_in[7];
    const float* Wc1       = (const float*)d_in[8];
    const float* bc1       = (const float*)d_in[9];
    const float* Wc2       = (const float*)d_in[10];
    const float* bc2       = (const float*)d_in[11];
    const float* Wc3       = (const float*)d_in[12];
    const float* bc3       = (const float*)d_in[13];
    const int*   src       = (const int*)d_in[14];
    const int*   dst       = (const int*)d_in[15];
    const int*   graph_ids = (const int*)d_in[16];
    float* out = (float*)d_out;

    float *p_h, *p_fs, *p_fd;
    unsigned *p_ah_hi, *p_ah_lo, *p_af_hi, *p_af_lo;
    unsigned *p_win_hi, *p_win_lo, *p_ws_hi, *p_ws_lo, *p_wd_hi, *p_wd_lo;
    cudaGetSymbolAddress((void**)&p_h,  g_h);
    cudaGetSymbolAddress((void**)&p_fs, g_fs);
    cudaGetSymbolAddress((void**)&p_fd, g_fd);
    cudaGetSymbolAddress((void**)&p_ah_hi, g_ah_hi);
    cudaGetSymbolAddress((void**)&p_ah_lo, g_ah_lo);
    cudaGetSymbolAddress((void**)&p_af_hi, g_af_hi);
    cudaGetSymbolAddress((void**)&p_af_lo, g_af_lo);
    cudaGetSymbolAddress((void**)&p_win_hi, g_win_hi);
    cudaGetSymbolAddress((void**)&p_win_lo, g_win_lo);
    cudaGetSymbolAddress((void**)&p_ws_hi, g_ws_hi);
    cudaGetSymbolAddress((void**)&p_ws_lo, g_ws_lo);
    cudaGetSymbolAddress((void**)&p_wd_hi, g_wd_hi);
    cudaGetSymbolAddress((void**)&p_wd_lo, g_wd_lo);

    cudaFuncSetAttribute(gemm_bf16x3_kernel,
                         cudaFuncAttributeMaxDynamicSharedMemorySize, GSMEM);

    cudaStream_t s2;
    cudaStreamCreateWithFlags(&s2, cudaStreamNonBlocking);
    cudaEvent_t evA, evB;
    cudaEventCreateWithFlags(&evA, cudaEventDisableTiming);
    cudaEventCreateWithFlags(&evB, cudaEventDisableTiming);

    // main: pack feature + W_in (GEMM1 deps only)
    const int NPIN = NN * K2IN + WIN_P;
    cudaEventRecord(evA, 0);
    pack_in_kernel<<<(NPIN + 255) / 256, 256>>>(W_in, feature);

    // stream 2: CSR chain + layer-weight pack, overlapped with pack_in + GEMM1
    cudaStreamWaitEvent(s2, evA, 0);
    zero_cnt_kernel<<<(NN + 255) / 256, 256, 0, s2>>>();
    count_kernel<<<(NE + 255) / 256, 256, 0, s2>>>(dst);
    scan_kernel<<<1, 1024, 0, s2>>>();
    fill_kernel<<<(NE + 255) / 256, 256, 0, s2>>>(src, dst);
    pack_lw_kernel<<<(2 * LAYERS * WL_P + 255) / 256, 256, 0, s2>>>(W_src, W_dst);
    gbound_kernel<<<1, 128, 0, s2>>>(graph_ids);
    cudaEventRecord(evB, s2);

    const int MROWS = (NN + GBM - 1) / GBM;
    const int NB = HID / GBN;
    dim3 grid1(NB, MROWS);
    dim3 grid2(2 * NB, MROWS);

    gemm_bf16x3_kernel<<<grid1, 256, GSMEM>>>(
        p_af_hi, p_af_lo, p_win_hi, p_win_lo, p_win_hi, p_win_lo,
        b_in, b_in, p_h, p_h, p_ah_hi, p_ah_lo,
        NN, K2IN, NB, 1);

    cudaStreamWaitEvent(0, evB, 0);

    const int fused_blocks = (NN + 7) / 8;
    for (int l = 0; l < LAYERS; l++) {
        const float* bs = b_src + (size_t)l * HID;
        const float* bd = b_dst + (size_t)l * HID;
        const float* al = attn + (size_t)l * HEADS * DH;

        gemm_bf16x3_kernel<<<grid2, 256, GSMEM>>>(
            p_ah_hi, p_ah_lo,
            p_ws_hi + (size_t)l * WL_P, p_ws_lo + (size_t)l * WL_P,
            p_wd_hi + (size_t)l * WL_P, p_wd_lo + (size_t)l * WL_P,
            bs, bd, p_fs, p_fd, (unsigned*)0, (unsigned*)0,
            NN, K2L, NB, 0);

        fused_edge_kernel<<<fused_blocks, 256>>>(al, (l + 1 < LAYERS) ? 1 : 0);
    }

    poolfc_kernel<<<NG, 256>>>(Wc1, bc1, Wc2, bc2, Wc3, bc3, out);
}

// round 16
// speedup vs baseline: 1.0197x; 1.0197x over previous
#include <cuda_runtime.h>
#include <cuda_bf16.h>
#include <math.h>

#define NN      20000
#define NE      320000
#define INDIM   128
#define HID     256
#define HEADS   8
#define DH      32
#define LAYERS  3
#define NG      64
#define OUTDIM  10
#define SLOPE   0.2f

#define K2IN  (INDIM / 2)
#define K2L   (HID / 2)
#define WIN_P (K2IN * HID)
#define WL_P  (K2L * HID)

// ---------------- scratch (device globals; no allocation allowed) ----------
__device__ float g_h[NN * HID];
__device__ float g_fs[NN * HID];
__device__ float g_fd[NN * HID];
__device__ unsigned g_ah_hi[NN * K2L];
__device__ unsigned g_ah_lo[NN * K2L];
__device__ unsigned g_af_hi[NN * K2IN];
__device__ unsigned g_af_lo[NN * K2IN];
__device__ unsigned g_win_hi[WIN_P], g_win_lo[WIN_P];
__device__ unsigned g_ws_hi[LAYERS * WL_P], g_ws_lo[LAYERS * WL_P];
__device__ unsigned g_wd_hi[LAYERS * WL_P], g_wd_lo[LAYERS * WL_P];
__device__ int g_cnt[NN];
__device__ int g_base[NN + 1];
__device__ int g_cur[NN];
__device__ int g_srcbyd[NE];
__device__ int g_gstart[NG + 1];

// ---------------- bf16 pack helpers -----------------------------------------
__device__ __forceinline__ unsigned pack_bf2(__nv_bfloat16 a, __nv_bfloat16 b) {
    return ((unsigned)__bfloat16_as_ushort(b) << 16) | (unsigned)__bfloat16_as_ushort(a);
}

__device__ __forceinline__ void split_pack(float x0, float x1, unsigned& hi, unsigned& lo) {
    __nv_bfloat16 h0 = __float2bfloat16_rn(x0);
    __nv_bfloat16 h1 = __float2bfloat16_rn(x1);
    __nv_bfloat16 l0 = __float2bfloat16_rn(x0 - __bfloat162float(h0));
    __nv_bfloat16 l1 = __float2bfloat16_rn(x1 - __bfloat162float(h1));
    hi = pack_bf2(h0, h1);
    lo = pack_bf2(l0, l1);
}

__device__ __forceinline__ void mma_bf16(float c[4], const unsigned a[4], const unsigned b[2]) {
    asm volatile(
        "mma.sync.aligned.m16n8k16.row.col.f32.bf16.bf16.f32 "
        "{%0,%1,%2,%3}, {%4,%5,%6,%7}, {%8,%9}, {%0,%1,%2,%3};"
        : "+f"(c[0]), "+f"(c[1]), "+f"(c[2]), "+f"(c[3])
        : "r"(a[0]), "r"(a[1]), "r"(a[2]), "r"(a[3]), "r"(b[0]), "r"(b[1]));
}

__device__ __forceinline__ void ldsm_x4(unsigned r[4], unsigned addr) {
    asm volatile("ldmatrix.sync.aligned.m8n8.x4.shared.b16 {%0,%1,%2,%3}, [%4];"
        : "=r"(r[0]), "=r"(r[1]), "=r"(r[2]), "=r"(r[3]) : "r"(addr));
}

__device__ __forceinline__ void cp_async16(unsigned saddr, const void* g, unsigned srcsz) {
    asm volatile("cp.async.cg.shared.global [%0], [%1], 16, %2;"
                 :: "r"(saddr), "l"(g), "r"(srcsz) : "memory");
}
#define CP_COMMIT() asm volatile("cp.async.commit_group;" ::: "memory")
#define CP_WAIT(n)  asm volatile("cp.async.wait_group %0;" :: "n"(n) : "memory")

// ---------------- pack: feature + W_in (main stream, feeds GEMM1) -------------
__global__ void pack_in_kernel(const float* __restrict__ W_in,
                               const float* __restrict__ feature)
{
    int i = blockIdx.x * blockDim.x + threadIdx.x;
    const int NF = NN * K2IN;
    if (i < NF) {
        float2 v = ((const float2*)feature)[i];
        split_pack(v.x, v.y, g_af_hi[i], g_af_lo[i]);
        return;
    }
    int j = i - NF;
    if (j >= WIN_P) return;
    int k2 = j >> 8, n = j & 255;
    split_pack(W_in[(2 * k2) * HID + n], W_in[(2 * k2 + 1) * HID + n],
               g_win_hi[j], g_win_lo[j]);
}

// ---------------- pack: layer weights (stream 2, overlapped) ------------------
__global__ void pack_lw_kernel(const float* __restrict__ W_src,
                               const float* __restrict__ W_dst)
{
    int j = blockIdx.x * blockDim.x + threadIdx.x;
    if (j >= 2 * LAYERS * WL_P) return;
    int which = j / (LAYERS * WL_P);
    int rem = j - which * (LAYERS * WL_P);
    int l = rem / WL_P;
    int p = rem - l * WL_P;
    int k2 = p >> 8, n = p & 255;
    const float* W = (which ? W_dst : W_src) + (size_t)l * HID * HID;
    unsigned* hi = (which ? g_wd_hi : g_ws_hi) + (size_t)l * WL_P;
    unsigned* lo = (which ? g_wd_lo : g_ws_lo) + (size_t)l * WL_P;
    split_pack(W[(2 * k2) * HID + n], W[(2 * k2 + 1) * HID + n], hi[p], lo[p]);
}

// ------- bf16x3 mma.sync GEMM: 64x128 tile, cp.async 3-stage pipeline --------
#define GBM 64
#define GBN 128
#define AST 20
#define BST 136
#define STG   27648
#define GSMEM (3 * STG)           // 82944 -> 2 CTAs/SM

__global__ __launch_bounds__(256) void gemm_bf16x3_kernel(
    const unsigned* __restrict__ Ahi, const unsigned* __restrict__ Alo,
    const unsigned* __restrict__ B1hi, const unsigned* __restrict__ B1lo,
    const unsigned* __restrict__ B2hi, const unsigned* __restrict__ B2lo,
    const float* __restrict__ bias1, const float* __restrict__ bias2,
    float* __restrict__ C1, float* __restrict__ C2,
    unsigned* __restrict__ Pho, unsigned* __restrict__ Plo,
    int M, int K2g, int nb, int do_pack)
{
    extern __shared__ __align__(16) unsigned char dsm[];
    const unsigned sbase = (unsigned)__cvta_generic_to_shared(dsm);

    int bx = blockIdx.x;
    int which = 0;
    if (bx >= nb) { which = 1; bx -= nb; }
    const unsigned* Bhi = which ? B2hi : B1hi;
    const unsigned* Blo = which ? B2lo : B1lo;
    const float* bias   = which ? bias2 : bias1;
    float* C            = which ? C2 : C1;

    const int tid  = threadIdx.x;
    const int wid  = tid >> 5;
    const int lane = tid & 31;
    const int wm   = (wid >> 2) * 32;
    const int wn   = (wid & 3) * 32;
    const int grp  = lane >> 2;
    const int tig  = lane & 3;
    const int row0 = blockIdx.y * GBM;
    const int col0 = bx * GBN;

    const int arw = tid >> 2;
    const int asg = (tid & 3) * 4;
    const int brw = tid >> 5;
    const int bcc = (tid & 31) * 4;

    const int lrow = wm + (lane & 15);
    const int lcol = (lane >> 4) * 4;

    const bool a_ok = (row0 + arw) < M;
    const int arow_c = a_ok ? (row0 + arw) : (M - 1);
    const unsigned a_srcsz = a_ok ? 16u : 0u;
    const unsigned a_soff = (arw * AST + asg) * 4u;
    const unsigned b_soff0 = 10240u + (brw * BST + bcc) * 4u;
    const unsigned b_soff1 = 10240u + ((brw + 8) * BST + bcc) * 4u;

    #define ISSUE_TILE(t, s) do {                                             \
        int kb = (t) * 16;                                                    \
        unsigned sb = sbase + (unsigned)(s) * STG;                            \
        size_t ga = (size_t)arow_c * K2g + kb + asg;                          \
        cp_async16(sb + a_soff,         Ahi + ga, a_srcsz);                   \
        cp_async16(sb + 5120 + a_soff,  Alo + ga, a_srcsz);                   \
        size_t gb0 = (size_t)(kb + brw) * 256 + col0 + bcc;                   \
        size_t gb1 = (size_t)(kb + brw + 8) * 256 + col0 + bcc;               \
        cp_async16(sb + b_soff0,        Bhi + gb0, 16u);                      \
        cp_async16(sb + 8704 + b_soff0, Blo + gb0, 16u);                      \
        cp_async16(sb + b_soff1,        Bhi + gb1, 16u);                      \
        cp_async16(sb + 8704 + b_soff1, Blo + gb1, 16u);                      \
    } while (0)

    float c[2][4][4];
    #pragma unroll
    for (int i = 0; i < 2; i++)
        #pragma unroll
        for (int j = 0; j < 4; j++)
            #pragma unroll
            for (int k = 0; k < 4; k++) c[i][j][k] = 0.f;

    const int nk = K2g >> 4;
    ISSUE_TILE(0, 0);
    CP_COMMIT();
    if (nk > 1) { ISSUE_TILE(1, 1); CP_COMMIT(); }

    int s = 0;
    for (int t = 0; t < nk; t++) {
        if (t + 1 < nk) CP_WAIT(1); else CP_WAIT(0);
        __syncthreads();

        const unsigned stg = sbase + (unsigned)s * STG;
        const unsigned* Bsh = (const unsigned*)(dsm + s * STG + 10240);
        const unsigned* Bsl = (const unsigned*)(dsm + s * STG + 18944);

        #pragma unroll
        for (int kk = 0; kk < 2; kk++) {
            unsigned ah[2][4], al[2][4], bh[4][2], bl[4][2];
            #pragma unroll
            for (int mt = 0; mt < 2; mt++) {
                unsigned off = ((unsigned)(lrow + mt * 16) * AST + kk * 8 + lcol) * 4u;
                ldsm_x4(ah[mt], stg + off);
                ldsm_x4(al[mt], stg + 5120 + off);
            }
            #pragma unroll
            for (int nt = 0; nt < 4; nt++) {
                int cn = wn + nt * 8 + grp;
                int r0 = (kk * 8 + tig) * BST;
                bh[nt][0] = Bsh[r0 + cn];      bh[nt][1] = Bsh[r0 + 4 * BST + cn];
                bl[nt][0] = Bsl[r0 + cn];      bl[nt][1] = Bsl[r0 + 4 * BST + cn];
            }
            #pragma unroll
            for (int mt = 0; mt < 2; mt++)
                #pragma unroll
                for (int nt = 0; nt < 4; nt++) {
                    mma_bf16(c[mt][nt], ah[mt], bl[nt]);
                    mma_bf16(c[mt][nt], al[mt], bh[nt]);
                    mma_bf16(c[mt][nt], ah[mt], bh[nt]);
                }
        }

        if (t + 2 < nk) {
            int s2i = s + 2; if (s2i >= 3) s2i -= 3;
            ISSUE_TILE(t + 2, s2i);
            CP_COMMIT();
        }
        s = (s + 1 == 3) ? 0 : s + 1;
    }

    #pragma unroll
    for (int nt = 0; nt < 4; nt++) {
        int cc = col0 + wn + nt * 8 + 2 * tig;
        float b0 = bias[cc], b1 = bias[cc + 1];
        #pragma unroll
        for (int mt = 0; mt < 2; mt++) {
            int r0 = row0 + wm + mt * 16 + grp;
            if (r0 < M) {
                float v0 = c[mt][nt][0] + b0, v1 = c[mt][nt][1] + b1;
                *(float2*)(C + (size_t)r0 * HID + cc) = make_float2(v0, v1);
                if (do_pack && which == 0) {
                    unsigned hi, lo;
                    split_pack(v0, v1, hi, lo);
                    size_t pi = ((size_t)r0 * HID + cc) >> 1;
                    Pho[pi] = hi; Plo[pi] = lo;
                }
            }
            int r1 = r0 + 8;
            if (r1 < M) {
                float v0 = c[mt][nt][2] + b0, v1 = c[mt][nt][3] + b1;
                *(float2*)(C + (size_t)r1 * HID + cc) = make_float2(v0, v1);
                if (do_pack && which == 0) {
                    unsigned hi, lo;
                    split_pack(v0, v1, hi, lo);
                    size_t pi = ((size_t)r1 * HID + cc) >> 1;
                    Pho[pi] = hi; Plo[pi] = lo;
                }
            }
        }
    }
    #undef ISSUE_TILE
}

// ---------------- CSR build (second stream) ----------------------------------
__global__ void zero_cnt_kernel() {
    int i = blockIdx.x * blockDim.x + threadIdx.x;
    if (i < NN) g_cnt[i] = 0;
}

__global__ void count_kernel(const int* __restrict__ dst) {
    int e = blockIdx.x * blockDim.x + threadIdx.x;
    if (e < NE) atomicAdd(&g_cnt[dst[e]], 1);
}

__global__ __launch_bounds__(1024) void scan_kernel() {
    __shared__ int s[1024];
    int t = threadIdx.x;
    int lo = t * 20;
    int hi = lo + 20; if (hi > NN) hi = NN;
    int sum = 0;
    for (int i = lo; i < hi; i++) sum += g_cnt[i];
    s[t] = sum;
    __syncthreads();
    for (int off = 1; off < 1024; off <<= 1) {
        int v = (t >= off) ? s[t - off] : 0;
        __syncthreads();
        s[t] += v;
        __syncthreads();
    }
    int run = s[t] - sum;
    for (int i = lo; i < hi; i++) {
        g_base[i] = run;
        g_cur[i] = run;
        run += g_cnt[i];
    }
    if (t == 0) g_base[NN] = NE;
}

__global__ void fill_kernel(const int* __restrict__ src, const int* __restrict__ dst) {
    int e = blockIdx.x * blockDim.x + threadIdx.x;
    if (e < NE) {
        int p = atomicAdd(&g_cur[dst[e]], 1);
        g_srcbyd[p] = src[e];
    }
}

__global__ void gbound_kernel(const int* __restrict__ gids) {
    int g = threadIdx.x;
    if (g > NG) return;
    int lo = 0, hi = NN;
    while (lo < hi) {
        int mid = (lo + hi) >> 1;
        if (gids[mid] < g) lo = mid + 1; else hi = mid;
    }
    g_gstart[g] = lo;
}

// ------- fused edge kernel: one warp per NODE, unroll-by-2 (R14 exact) -------
__global__ __launch_bounds__(256) void fused_edge_kernel(const float* __restrict__ attn,
                                                         int do_pack)
{
    int n = blockIdx.x * 8 + (threadIdx.x >> 5);
    int lane = threadIdx.x & 31;
    if (n >= NN) return;
    const size_t rowoff = (size_t)n * HID + lane * 8;

    float fdv[8], av[8];
    {
        float4 t0 = *(const float4*)(g_fd + rowoff);
        float4 t1 = *(const float4*)(g_fd + rowoff + 4);
        fdv[0]=t0.x; fdv[1]=t0.y; fdv[2]=t0.z; fdv[3]=t0.w;
        fdv[4]=t1.x; fdv[5]=t1.y; fdv[6]=t1.z; fdv[7]=t1.w;
        float4 a0 = *(const float4*)(attn + lane * 8);
        float4 a1 = *(const float4*)(attn + lane * 8 + 4);
        av[0]=a0.x; av[1]=a0.y; av[2]=a0.z; av[3]=a0.w;
        av[4]=a1.x; av[5]=a1.y; av[6]=a1.z; av[7]=a1.w;
    }

    const int b  = __ldg(&g_base[n]);
    const int e2 = __ldg(&g_base[n + 1]);

    float m = -1e30f, sd = 0.f;
    float acc[8] = {0.f,0.f,0.f,0.f,0.f,0.f,0.f,0.f};

    int j = b;
    for (; j + 2 <= e2; j += 2) {
        int s0 = __ldg(&g_srcbyd[j]);
        int s1 = __ldg(&g_srcbyd[j + 1]);
        const float4* f0 = (const float4*)(g_fs + (size_t)s0 * HID + lane * 8);
        const float4* f1 = (const float4*)(g_fs + (size_t)s1 * HID + lane * 8);
        float4 a00 = f0[0], a01 = f0[1];
        float4 a10 = f1[0], a11 = f1[1];
        float fsv0[8] = {a00.x,a00.y,a00.z,a00.w,a01.x,a01.y,a01.z,a01.w};
        float fsv1[8] = {a10.x,a10.y,a10.z,a10.w,a11.x,a11.y,a11.z,a11.w};

        float p0 = 0.f, p1 = 0.f;
        #pragma unroll
        for (int q = 0; q < 8; q++) {
            float v0 = fsv0[q] + fdv[q];
            v0 = (v0 > 0.f) ? v0 : SLOPE * v0;
            p0 = fmaf(v0, av[q], p0);
            float v1 = fsv1[q] + fdv[q];
            v1 = (v1 > 0.f) ? v1 : SLOPE * v1;
            p1 = fmaf(v1, av[q], p1);
        }
        p0 += __shfl_xor_sync(0xffffffffu, p0, 1);
        p0 += __shfl_xor_sync(0xffffffffu, p0, 2);
        p1 += __shfl_xor_sync(0xffffffffu, p1, 1);
        p1 += __shfl_xor_sync(0xffffffffu, p1, 2);

        {
            float nm = fmaxf(m, p0);
            float fac = __expf(m - nm);
            float w   = __expf(p0 - nm);
            sd = sd * fac + w;
            #pragma unroll
            for (int q = 0; q < 8; q++) acc[q] = fmaf(acc[q], fac, w * fsv0[q]);
            m = nm;
        }
        {
            float nm = fmaxf(m, p1);
            float fac = __expf(m - nm);
            float w   = __expf(p1 - nm);
            sd = sd * fac + w;
            #pragma unroll
            for (int q = 0; q < 8; q++) acc[q] = fmaf(acc[q], fac, w * fsv1[q]);
            m = nm;
        }
    }
    if (j < e2) {
        int s0 = __ldg(&g_srcbyd[j]);
        const float4* f0 = (const float4*)(g_fs + (size_t)s0 * HID + lane * 8);
        float4 a00 = f0[0], a01 = f0[1];
        float fsv0[8] = {a00.x,a00.y,a00.z,a00.w,a01.x,a01.y,a01.z,a01.w};
        float p0 = 0.f;
        #pragma unroll
        for (int q = 0; q < 8; q++) {
            float v0 = fsv0[q] + fdv[q];
            v0 = (v0 > 0.f) ? v0 : SLOPE * v0;
            p0 = fmaf(v0, av[q], p0);
        }
        p0 += __shfl_xor_sync(0xffffffffu, p0, 1);
        p0 += __shfl_xor_sync(0xffffffffu, p0, 2);
        float nm = fmaxf(m, p0);
        float fac = __expf(m - nm);
        float w   = __expf(p0 - nm);
        sd = sd * fac + w;
        #pragma unroll
        for (int q = 0; q < 8; q++) acc[q] = fmaf(acc[q], fac, w * fsv0[q]);
        m = nm;
    }

    float inv = (sd > 0.f) ? 1.f / sd : 0.f;
    float hv[8];
    {
        float4 h0 = *(const float4*)(g_h + rowoff);
        float4 h1 = *(const float4*)(g_h + rowoff + 4);
        float hold[8] = {h0.x,h0.y,h0.z,h0.w,h1.x,h1.y,h1.z,h1.w};
        #pragma unroll
        for (int q = 0; q < 8; q++) hv[q] = fmaxf(fmaf(acc[q], inv, hold[q]), 0.f);
    }
    *(float4*)(g_h + rowoff)     = make_float4(hv[0], hv[1], hv[2], hv[3]);
    *(float4*)(g_h + rowoff + 4) = make_float4(hv[4], hv[5], hv[6], hv[7]);
    if (do_pack) {
        size_t pbase = rowoff >> 1;
        #pragma unroll
        for (int q = 0; q < 8; q += 2) {
            unsigned hi, lo;
            split_pack(hv[q], hv[q + 1], hi, lo);
            g_ah_hi[pbase + (q >> 1)] = hi;
            g_ah_lo[pbase + (q >> 1)] = lo;
        }
    }
}

// ---------------- fused pool + 3-layer classifier, one block per graph -------
__global__ __launch_bounds__(256) void poolfc_kernel(
    const float* __restrict__ Wc1, const float* __restrict__ bc1,
    const float* __restrict__ Wc2, const float* __restrict__ bc2,
    const float* __restrict__ Wc3, const float* __restrict__ bc3,
    float* __restrict__ out)
{
    __shared__ float sh[256];
    __shared__ float sx[256];
    int g = blockIdx.x;
    int c = threadIdx.x;
    int n0 = g_gstart[g], n1 = g_gstart[g + 1];
    float s = 0.f;
    for (int n = n0; n < n1; n++) s += g_h[(size_t)n * HID + c];
    sh[c] = s;
    __syncthreads();
    float a = bc1[c];
    #pragma unroll 8
    for (int k = 0; k < HID; k++) a = fmaf(sh[k], Wc1[k * HID + c], a);
    sx[c] = fmaxf(a, 0.f);
    __syncthreads();
    float b2 = 0.f;
    if (c < HID / 2) {
        b2 = bc2[c];
        #pragma unroll 8
        for (int k = 0; k < HID; k++) b2 = fmaf(sx[k], Wc2[k * (HID / 2) + c], b2);
        b2 = fmaxf(b2, 0.f);
    }
    __syncthreads();
    if (c < HID / 2) sh[c] = b2;
    __syncthreads();
    if (c < OUTDIM) {
        float o = bc3[c];
        for (int k = 0; k < HID / 2; k++) o = fmaf(sh[k], Wc3[k * OUTDIM + c], o);
        out[g * OUTDIM + c] = o;
    }
}

// ---------------- launch -------------------------------------------------------
extern "C" void kernel_launch(void* const* d_in, const int* in_sizes, int n_in,
                              void* d_out, int out_size)
{
    const float* feature   = (const float*)d_in[0];
    const float* W_in      = (const float*)d_in[1];
    const float* b_in      = (const float*)d_in[2];
    const float* W_src     = (const float*)d_in[3];
    const float* b_src     = (const float*)d_in[4];
    const float* W_dst     = (const float*)d_in[5];
    const float* b_dst     = (const float*)d_in[6];
    const float* attn      = (const float*)d_in[7];
    const float* Wc1       = (const float*)d_in[8];
    const float* bc1       = (const float*)d_in[9];
    const float* Wc2       = (const float*)d_in[10];
    const float* bc2       = (const float*)d_in[11];
    const float* Wc3       = (const float*)d_in[12];
    const float* bc3       = (const float*)d_in[13];
    const int*   src       = (const int*)d_in[14];
    const int*   dst       = (const int*)d_in[15];
    const int*   graph_ids = (const int*)d_in[16];
    float* out = (float*)d_out;

    float *p_h, *p_fs, *p_fd;
    unsigned *p_ah_hi, *p_ah_lo, *p_af_hi, *p_af_lo;
    unsigned *p_win_hi, *p_win_lo, *p_ws_hi, *p_ws_lo, *p_wd_hi, *p_wd_lo;
    cudaGetSymbolAddress((void**)&p_h,  g_h);
    cudaGetSymbolAddress((void**)&p_fs, g_fs);
    cudaGetSymbolAddress((void**)&p_fd, g_fd);
    cudaGetSymbolAddress((void**)&p_ah_hi, g_ah_hi);
    cudaGetSymbolAddress((void**)&p_ah_lo, g_ah_lo);
    cudaGetSymbolAddress((void**)&p_af_hi, g_af_hi);
    cudaGetSymbolAddress((void**)&p_af_lo, g_af_lo);
    cudaGetSymbolAddress((void**)&p_win_hi, g_win_hi);
    cudaGetSymbolAddress((void**)&p_win_lo, g_win_lo);
    cudaGetSymbolAddress((void**)&p_ws_hi, g_ws_hi);
    cudaGetSymbolAddress((void**)&p_ws_lo, g_ws_lo);
    cudaGetSymbolAddress((void**)&p_wd_hi, g_wd_hi);
    cudaGetSymbolAddress((void**)&p_wd_lo, g_wd_lo);

    cudaFuncSetAttribute(gemm_bf16x3_kernel,
                         cudaFuncAttributeMaxDynamicSharedMemorySize, GSMEM);

    cudaStream_t s2;
    cudaStreamCreateWithFlags(&s2, cudaStreamNonBlocking);
    cudaEvent_t evA, evB;
    cudaEventCreateWithFlags(&evA, cudaEventDisableTiming);
    cudaEventCreateWithFlags(&evB, cudaEventDisableTiming);

    // main: pack feature + W_in (GEMM1 deps only)
    const int NPIN = NN * K2IN + WIN_P;
    cudaEventRecord(evA, 0);
    pack_in_kernel<<<(NPIN + 255) / 256, 256>>>(W_in, feature);

    // stream 2: CSR chain + layer-weight pack, overlapped with pack_in + GEMM1
    cudaStreamWaitEvent(s2, evA, 0);
    zero_cnt_kernel<<<(NN + 255) / 256, 256, 0, s2>>>();
    count_kernel<<<(NE + 255) / 256, 256, 0, s2>>>(dst);
    scan_kernel<<<1, 1024, 0, s2>>>();
    fill_kernel<<<(NE + 255) / 256, 256, 0, s2>>>(src, dst);
    pack_lw_kernel<<<(2 * LAYERS * WL_P + 255) / 256, 256, 0, s2>>>(W_src, W_dst);
    gbound_kernel<<<1, 128, 0, s2>>>(graph_ids);
    cudaEventRecord(evB, s2);

    const int MROWS = (NN + GBM - 1) / GBM;
    const int NB = HID / GBN;
    dim3 grid1(NB, MROWS);
    dim3 grid2(2 * NB, MROWS);

    gemm_bf16x3_kernel<<<grid1, 256, GSMEM>>>(
        p_af_hi, p_af_lo, p_win_hi, p_win_lo, p_win_hi, p_win_lo,
        b_in, b_in, p_h, p_h, p_ah_hi, p_ah_lo,
        NN, K2IN, NB, 1);

    cudaStreamWaitEvent(0, evB, 0);

    const int fused_blocks = (NN + 7) / 8;
    for (int l = 0; l < LAYERS; l++) {
        const float* bs = b_src + (size_t)l * HID;
        const float* bd = b_dst + (size_t)l * HID;
        const float* al = attn + (size_t)l * HEADS * DH;

        gemm_bf16x3_kernel<<<grid2, 256, GSMEM>>>(
            p_ah_hi, p_ah_lo,
            p_ws_hi + (size_t)l * WL_P, p_ws_lo + (size_t)l * WL_P,
            p_wd_hi + (size_t)l * WL_P, p_wd_lo + (size_t)l * WL_P,
            bs, bd, p_fs, p_fd, (unsigned*)0, (unsigned*)0,
            NN, K2L, NB, 0);

        fused_edge_kernel<<<fused_blocks, 256>>>(al, (l + 1 < LAYERS) ? 1 : 0);
    }

    poolfc_kernel<<<NG, 256>>>(Wc1, bc1, Wc2, bc2, Wc3, bc3, out);
}

// round 17
// speedup vs baseline: 1.0607x; 1.0402x over previous
#include <cuda_runtime.h>
#include <cuda_bf16.h>
#include <math.h>

#define NN      20000
#define NE      320000
#define INDIM   128
#define HID     256
#define HEADS   8
#define DH      32
#define LAYERS  3
#define NG      64
#define OUTDIM  10
#define SLOPE   0.2f

#define K2IN  (INDIM / 2)
#define K2L   (HID / 2)
#define WIN_P (K2IN * HID)
#define WL_P  (K2L * HID)

// ---------------- scratch (device globals; no allocation allowed) ----------
__device__ float g_h[NN * HID];
__device__ float g_fs[NN * HID];
__device__ float g_fd[NN * HID];
__device__ unsigned g_ah_hi[NN * K2L];
__device__ unsigned g_ah_lo[NN * K2L];
__device__ unsigned g_af_hi[NN * K2IN];
__device__ unsigned g_af_lo[NN * K2IN];
__device__ unsigned g_win_hi[WIN_P], g_win_lo[WIN_P];
__device__ unsigned g_ws_hi[LAYERS * WL_P], g_ws_lo[LAYERS * WL_P];
__device__ unsigned g_wd_hi[LAYERS * WL_P], g_wd_lo[LAYERS * WL_P];
__device__ int g_cnt[NN];
__device__ int g_base[NN + 1];
__device__ int g_cur[NN];
__device__ int g_srcbyd[NE];
__device__ int g_gstart[NG + 1];

// ---------------- bf16 pack helpers -----------------------------------------
__device__ __forceinline__ unsigned pack_bf2(__nv_bfloat16 a, __nv_bfloat16 b) {
    return ((unsigned)__bfloat16_as_ushort(b) << 16) | (unsigned)__bfloat16_as_ushort(a);
}

__device__ __forceinline__ void split_pack(float x0, float x1, unsigned& hi, unsigned& lo) {
    __nv_bfloat16 h0 = __float2bfloat16_rn(x0);
    __nv_bfloat16 h1 = __float2bfloat16_rn(x1);
    __nv_bfloat16 l0 = __float2bfloat16_rn(x0 - __bfloat162float(h0));
    __nv_bfloat16 l1 = __float2bfloat16_rn(x1 - __bfloat162float(h1));
    hi = pack_bf2(h0, h1);
    lo = pack_bf2(l0, l1);
}

__device__ __forceinline__ void mma_bf16(float c[4], const unsigned a[4], const unsigned b[2]) {
    asm volatile(
        "mma.sync.aligned.m16n8k16.row.col.f32.bf16.bf16.f32 "
        "{%0,%1,%2,%3}, {%4,%5,%6,%7}, {%8,%9}, {%0,%1,%2,%3};"
        : "+f"(c[0]), "+f"(c[1]), "+f"(c[2]), "+f"(c[3])
        : "r"(a[0]), "r"(a[1]), "r"(a[2]), "r"(a[3]), "r"(b[0]), "r"(b[1]));
}

__device__ __forceinline__ void ldsm_x4(unsigned r[4], unsigned addr) {
    asm volatile("ldmatrix.sync.aligned.m8n8.x4.shared.b16 {%0,%1,%2,%3}, [%4];"
        : "=r"(r[0]), "=r"(r[1]), "=r"(r[2]), "=r"(r[3]) : "r"(addr));
}

__device__ __forceinline__ void cp_async16(unsigned saddr, const void* g, unsigned srcsz) {
    asm volatile("cp.async.cg.shared.global [%0], [%1], 16, %2;"
                 :: "r"(saddr), "l"(g), "r"(srcsz) : "memory");
}
#define CP_COMMIT() asm volatile("cp.async.commit_group;" ::: "memory")
#define CP_WAIT(n)  asm volatile("cp.async.wait_group %0;" :: "n"(n) : "memory")

// ---------------- pack everything in one launch (R14) -------------------------
__global__ void pack_all_kernel(const float* __restrict__ W_in,
                                const float* __restrict__ W_src,
                                const float* __restrict__ W_dst,
                                const float* __restrict__ feature)
{
    int i = blockIdx.x * blockDim.x + threadIdx.x;
    const int NF = NN * K2IN;
    if (i < NF) {
        float2 v = ((const float2*)feature)[i];
        split_pack(v.x, v.y, g_af_hi[i], g_af_lo[i]);
        return;
    }
    int j = i - NF;
    if (j < WIN_P) {
        int k2 = j >> 8, n = j & 255;
        split_pack(W_in[(2 * k2) * HID + n], W_in[(2 * k2 + 1) * HID + n],
                   g_win_hi[j], g_win_lo[j]);
        return;
    }
    j -= WIN_P;
    if (j >= 2 * LAYERS * WL_P) return;
    int which = j / (LAYERS * WL_P);
    int rem = j - which * (LAYERS * WL_P);
    int l = rem / WL_P;
    int p = rem - l * WL_P;
    int k2 = p >> 8, n = p & 255;
    const float* W = (which ? W_dst : W_src) + (size_t)l * HID * HID;
    unsigned* hi = (which ? g_wd_hi : g_ws_hi) + (size_t)l * WL_P;
    unsigned* lo = (which ? g_wd_lo : g_ws_lo) + (size_t)l * WL_P;
    split_pack(W[(2 * k2) * HID + n], W[(2 * k2 + 1) * HID + n], hi[p], lo[p]);
}

// ------- bf16x3 mma.sync GEMM: 64x128 tile, cp.async 3-stage pipeline --------
#define GBM 64
#define GBN 128
#define AST 20
#define BST 136
#define STG   27648
#define GSMEM (3 * STG)           // 82944 -> 2 CTAs/SM

__global__ __launch_bounds__(256) void gemm_bf16x3_kernel(
    const unsigned* __restrict__ Ahi, const unsigned* __restrict__ Alo,
    const unsigned* __restrict__ B1hi, const unsigned* __restrict__ B1lo,
    const unsigned* __restrict__ B2hi, const unsigned* __restrict__ B2lo,
    const float* __restrict__ bias1, const float* __restrict__ bias2,
    float* __restrict__ C1, float* __restrict__ C2,
    unsigned* __restrict__ Pho, unsigned* __restrict__ Plo,
    int M, int K2g, int nb, int do_pack)
{
    extern __shared__ __align__(16) unsigned char dsm[];
    const unsigned sbase = (unsigned)__cvta_generic_to_shared(dsm);

    int bx = blockIdx.x;
    int which = 0;
    if (bx >= nb) { which = 1; bx -= nb; }
    const unsigned* Bhi = which ? B2hi : B1hi;
    const unsigned* Blo = which ? B2lo : B1lo;
    const float* bias   = which ? bias2 : bias1;
    float* C            = which ? C2 : C1;

    const int tid  = threadIdx.x;
    const int wid  = tid >> 5;
    const int lane = tid & 31;
    const int wm   = (wid >> 2) * 32;
    const int wn   = (wid & 3) * 32;
    const int grp  = lane >> 2;
    const int tig  = lane & 3;
    const int row0 = blockIdx.y * GBM;
    const int col0 = bx * GBN;

    const int arw = tid >> 2;
    const int asg = (tid & 3) * 4;
    const int brw = tid >> 5;
    const int bcc = (tid & 31) * 4;

    const int lrow = wm + (lane & 15);
    const int lcol = (lane >> 4) * 4;

    const bool a_ok = (row0 + arw) < M;
    const int arow_c = a_ok ? (row0 + arw) : (M - 1);
    const unsigned a_srcsz = a_ok ? 16u : 0u;
    const unsigned a_soff = (arw * AST + asg) * 4u;
    const unsigned b_soff0 = 10240u + (brw * BST + bcc) * 4u;
    const unsigned b_soff1 = 10240u + ((brw + 8) * BST + bcc) * 4u;

    #define ISSUE_TILE(t, s) do {                                             \
        int kb = (t) * 16;                                                    \
        unsigned sb = sbase + (unsigned)(s) * STG;                            \
        size_t ga = (size_t)arow_c * K2g + kb + asg;                          \
        cp_async16(sb + a_soff,         Ahi + ga, a_srcsz);                   \
        cp_async16(sb + 5120 + a_soff,  Alo + ga, a_srcsz);                   \
        size_t gb0 = (size_t)(kb + brw) * 256 + col0 + bcc;                   \
        size_t gb1 = (size_t)(kb + brw + 8) * 256 + col0 + bcc;               \
        cp_async16(sb + b_soff0,        Bhi + gb0, 16u);                      \
        cp_async16(sb + 8704 + b_soff0, Blo + gb0, 16u);                      \
        cp_async16(sb + b_soff1,        Bhi + gb1, 16u);                      \
        cp_async16(sb + 8704 + b_soff1, Blo + gb1, 16u);                      \
    } while (0)

    float c[2][4][4];
    #pragma unroll
    for (int i = 0; i < 2; i++)
        #pragma unroll
        for (int j = 0; j < 4; j++)
            #pragma unroll
            for (int k = 0; k < 4; k++) c[i][j][k] = 0.f;

    const int nk = K2g >> 4;
    ISSUE_TILE(0, 0);
    CP_COMMIT();
    if (nk > 1) { ISSUE_TILE(1, 1); CP_COMMIT(); }

    int s = 0;
    for (int t = 0; t < nk; t++) {
        if (t + 1 < nk) CP_WAIT(1); else CP_WAIT(0);
        __syncthreads();

        const unsigned stg = sbase + (unsigned)s * STG;
        const unsigned* Bsh = (const unsigned*)(dsm + s * STG + 10240);
        const unsigned* Bsl = (const unsigned*)(dsm + s * STG + 18944);

        #pragma unroll
        for (int kk = 0; kk < 2; kk++) {
            unsigned ah[2][4], al[2][4], bh[4][2], bl[4][2];
            #pragma unroll
            for (int mt = 0; mt < 2; mt++) {
                unsigned off = ((unsigned)(lrow + mt * 16) * AST + kk * 8 + lcol) * 4u;
                ldsm_x4(ah[mt], stg + off);
                ldsm_x4(al[mt], stg + 5120 + off);
            }
            #pragma unroll
            for (int nt = 0; nt < 4; nt++) {
                int cn = wn + nt * 8 + grp;
                int r0 = (kk * 8 + tig) * BST;
                bh[nt][0] = Bsh[r0 + cn];      bh[nt][1] = Bsh[r0 + 4 * BST + cn];
                bl[nt][0] = Bsl[r0 + cn];      bl[nt][1] = Bsl[r0 + 4 * BST + cn];
            }
            #pragma unroll
            for (int mt = 0; mt < 2; mt++)
                #pragma unroll
                for (int nt = 0; nt < 4; nt++) {
                    mma_bf16(c[mt][nt], ah[mt], bl[nt]);
                    mma_bf16(c[mt][nt], al[mt], bh[nt]);
                    mma_bf16(c[mt][nt], ah[mt], bh[nt]);
                }
        }

        if (t + 2 < nk) {
            int s2i = s + 2; if (s2i >= 3) s2i -= 3;
            ISSUE_TILE(t + 2, s2i);
            CP_COMMIT();
        }
        s = (s + 1 == 3) ? 0 : s + 1;
    }

    #pragma unroll
    for (int nt = 0; nt < 4; nt++) {
        int cc = col0 + wn + nt * 8 + 2 * tig;
        float b0 = bias[cc], b1 = bias[cc + 1];
        #pragma unroll
        for (int mt = 0; mt < 2; mt++) {
            int r0 = row0 + wm + mt * 16 + grp;
            if (r0 < M) {
                float v0 = c[mt][nt][0] + b0, v1 = c[mt][nt][1] + b1;
                *(float2*)(C + (size_t)r0 * HID + cc) = make_float2(v0, v1);
                if (do_pack && which == 0) {
                    unsigned hi, lo;
                    split_pack(v0, v1, hi, lo);
                    size_t pi = ((size_t)r0 * HID + cc) >> 1;
                    Pho[pi] = hi; Plo[pi] = lo;
                }
            }
            int r1 = r0 + 8;
            if (r1 < M) {
                float v0 = c[mt][nt][2] + b0, v1 = c[mt][nt][3] + b1;
                *(float2*)(C + (size_t)r1 * HID + cc) = make_float2(v0, v1);
                if (do_pack && which == 0) {
                    unsigned hi, lo;
                    split_pack(v0, v1, hi, lo);
                    size_t pi = ((size_t)r1 * HID + cc) >> 1;
                    Pho[pi] = hi; Plo[pi] = lo;
                }
            }
        }
    }
    #undef ISSUE_TILE
}

// ---------------- CSR build (second stream) ----------------------------------
__global__ void zero_cnt_kernel() {
    int i = blockIdx.x * blockDim.x + threadIdx.x;
    if (i < NN) g_cnt[i] = 0;
}

__global__ void count_kernel(const int* __restrict__ dst) {
    int e = blockIdx.x * blockDim.x + threadIdx.x;
    if (e < NE) atomicAdd(&g_cnt[dst[e]], 1);
}

__global__ __launch_bounds__(1024) void scan_kernel() {
    __shared__ int s[1024];
    int t = threadIdx.x;
    int lo = t * 20;
    int hi = lo + 20; if (hi > NN) hi = NN;
    int sum = 0;
    for (int i = lo; i < hi; i++) sum += g_cnt[i];
    s[t] = sum;
    __syncthreads();
    for (int off = 1; off < 1024; off <<= 1) {
        int v = (t >= off) ? s[t - off] : 0;
        __syncthreads();
        s[t] += v;
        __syncthreads();
    }
    int run = s[t] - sum;
    for (int i = lo; i < hi; i++) {
        g_base[i] = run;
        g_cur[i] = run;
        run += g_cnt[i];
    }
    if (t == 0) g_base[NN] = NE;
}

__global__ void fill_kernel(const int* __restrict__ src, const int* __restrict__ dst) {
    int e = blockIdx.x * blockDim.x + threadIdx.x;
    if (e < NE) {
        int p = atomicAdd(&g_cur[dst[e]], 1);
        g_srcbyd[p] = src[e];
    }
}

__global__ void gbound_kernel(const int* __restrict__ gids) {
    int g = threadIdx.x;
    if (g > NG) return;
    int lo = 0, hi = NN;
    while (lo < hi) {
        int mid = (lo + hi) >> 1;
        if (gids[mid] < g) lo = mid + 1; else hi = mid;
    }
    g_gstart[g] = lo;
}

// ------- fused edge kernel: warp per node, unroll-2, 64-thread blocks --------
__global__ __launch_bounds__(64) void fused_edge_kernel(const float* __restrict__ attn,
                                                        int do_pack)
{
    int n = blockIdx.x * 2 + (threadIdx.x >> 5);
    int lane = threadIdx.x & 31;
    if (n >= NN) return;
    const size_t rowoff = (size_t)n * HID + lane * 8;

    float fdv[8], av[8];
    {
        float4 t0 = *(const float4*)(g_fd + rowoff);
        float4 t1 = *(const float4*)(g_fd + rowoff + 4);
        fdv[0]=t0.x; fdv[1]=t0.y; fdv[2]=t0.z; fdv[3]=t0.w;
        fdv[4]=t1.x; fdv[5]=t1.y; fdv[6]=t1.z; fdv[7]=t1.w;
        float4 a0 = *(const float4*)(attn + lane * 8);
        float4 a1 = *(const float4*)(attn + lane * 8 + 4);
        av[0]=a0.x; av[1]=a0.y; av[2]=a0.z; av[3]=a0.w;
        av[4]=a1.x; av[5]=a1.y; av[6]=a1.z; av[7]=a1.w;
    }

    const int b  = __ldg(&g_base[n]);
    const int e2 = __ldg(&g_base[n + 1]);

    float m = -1e30f, sd = 0.f;
    float acc[8] = {0.f,0.f,0.f,0.f,0.f,0.f,0.f,0.f};

    int j = b;
    for (; j + 2 <= e2; j += 2) {
        int s0 = __ldg(&g_srcbyd[j]);
        int s1 = __ldg(&g_srcbyd[j + 1]);
        const float4* f0 = (const float4*)(g_fs + (size_t)s0 * HID + lane * 8);
        const float4* f1 = (const float4*)(g_fs + (size_t)s1 * HID + lane * 8);
        float4 a00 = f0[0], a01 = f0[1];
        float4 a10 = f1[0], a11 = f1[1];
        float fsv0[8] = {a00.x,a00.y,a00.z,a00.w,a01.x,a01.y,a01.z,a01.w};
        float fsv1[8] = {a10.x,a10.y,a10.z,a10.w,a11.x,a11.y,a11.z,a11.w};

        float p0 = 0.f, p1 = 0.f;
        #pragma unroll
        for (int q = 0; q < 8; q++) {
            float v0 = fsv0[q] + fdv[q];
            v0 = (v0 > 0.f) ? v0 : SLOPE * v0;
            p0 = fmaf(v0, av[q], p0);
            float v1 = fsv1[q] + fdv[q];
            v1 = (v1 > 0.f) ? v1 : SLOPE * v1;
            p1 = fmaf(v1, av[q], p1);
        }
        p0 += __shfl_xor_sync(0xffffffffu, p0, 1);
        p0 += __shfl_xor_sync(0xffffffffu, p0, 2);
        p1 += __shfl_xor_sync(0xffffffffu, p1, 1);
        p1 += __shfl_xor_sync(0xffffffffu, p1, 2);

        {
            float nm = fmaxf(m, p0);
            float fac = __expf(m - nm);
            float w   = __expf(p0 - nm);
            sd = sd * fac + w;
            #pragma unroll
            for (int q = 0; q < 8; q++) acc[q] = fmaf(acc[q], fac, w * fsv0[q]);
            m = nm;
        }
        {
            float nm = fmaxf(m, p1);
            float fac = __expf(m - nm);
            float w   = __expf(p1 - nm);
            sd = sd * fac + w;
            #pragma unroll
            for (int q = 0; q < 8; q++) acc[q] = fmaf(acc[q], fac, w * fsv1[q]);
            m = nm;
        }
    }
    if (j < e2) {
        int s0 = __ldg(&g_srcbyd[j]);
        const float4* f0 = (const float4*)(g_fs + (size_t)s0 * HID + lane * 8);
        float4 a00 = f0[0], a01 = f0[1];
        float fsv0[8] = {a00.x,a00.y,a00.z,a00.w,a01.x,a01.y,a01.z,a01.w};
        float p0 = 0.f;
        #pragma unroll
        for (int q = 0; q < 8; q++) {
            float v0 = fsv0[q] + fdv[q];
            v0 = (v0 > 0.f) ? v0 : SLOPE * v0;
            p0 = fmaf(v0, av[q], p0);
        }
        p0 += __shfl_xor_sync(0xffffffffu, p0, 1);
        p0 += __shfl_xor_sync(0xffffffffu, p0, 2);
        float nm = fmaxf(m, p0);
        float fac = __expf(m - nm);
        float w   = __expf(p0 - nm);
        sd = sd * fac + w;
        #pragma unroll
        for (int q = 0; q < 8; q++) acc[q] = fmaf(acc[q], fac, w * fsv0[q]);
        m = nm;
    }

    float inv = (sd > 0.f) ? 1.f / sd : 0.f;
    float hv[8];
    {
        float4 h0 = *(const float4*)(g_h + rowoff);
        float4 h1 = *(const float4*)(g_h + rowoff + 4);
        float hold[8] = {h0.x,h0.y,h0.z,h0.w,h1.x,h1.y,h1.z,h1.w};
        #pragma unroll
        for (int q = 0; q < 8; q++) hv[q] = fmaxf(fmaf(acc[q], inv, hold[q]), 0.f);
    }
    *(float4*)(g_h + rowoff)     = make_float4(hv[0], hv[1], hv[2], hv[3]);
    *(float4*)(g_h + rowoff + 4) = make_float4(hv[4], hv[5], hv[6], hv[7]);
    if (do_pack) {
        size_t pbase = rowoff >> 1;
        #pragma unroll
        for (int q = 0; q < 8; q += 2) {
            unsigned hi, lo;
            split_pack(hv[q], hv[q + 1], hi, lo);
            g_ah_hi[pbase + (q >> 1)] = hi;
            g_ah_lo[pbase + (q >> 1)] = lo;
        }
    }
}

// ---------------- fused pool + 3-layer classifier, one block per graph -------
__global__ __launch_bounds__(256) void poolfc_kernel(
    const float* __restrict__ Wc1, const float* __restrict__ bc1,
    const float* __restrict__ Wc2, const float* __restrict__ bc2,
    const float* __restrict__ Wc3, const float* __restrict__ bc3,
    float* __restrict__ out)
{
    __shared__ float sh[256];
    __shared__ float sx[256];
    int g = blockIdx.x;
    int c = threadIdx.x;
    int n0 = g_gstart[g], n1 = g_gstart[g + 1];
    float s = 0.f;
    for (int n = n0; n < n1; n++) s += g_h[(size_t)n * HID + c];
    sh[c] = s;
    __syncthreads();
    float a = bc1[c];
    #pragma unroll 8
    for (int k = 0; k < HID; k++) a = fmaf(sh[k], Wc1[k * HID + c], a);
    sx[c] = fmaxf(a, 0.f);
    __syncthreads();
    float b2 = 0.f;
    if (c < HID / 2) {
        b2 = bc2[c];
        #pragma unroll 8
        for (int k = 0; k < HID; k++) b2 = fmaf(sx[k], Wc2[k * (HID / 2) + c], b2);
        b2 = fmaxf(b2, 0.f);
    }
    __syncthreads();
    if (c < HID / 2) sh[c] = b2;
    __syncthreads();
    if (c < OUTDIM) {
        float o = bc3[c];
        for (int k = 0; k < HID / 2; k++) o = fmaf(sh[k], Wc3[k * OUTDIM + c], o);
        out[g * OUTDIM + c] = o;
    }
}

// ---------------- launch -------------------------------------------------------
extern "C" void kernel_launch(void* const* d_in, const int* in_sizes, int n_in,
                              void* d_out, int out_size)
{
    const float* feature   = (const float*)d_in[0];
    const float* W_in      = (const float*)d_in[1];
    const float* b_in      = (const float*)d_in[2];
    const float* W_src     = (const float*)d_in[3];
    const float* b_src     = (const float*)d_in[4];
    const float* W_dst     = (const float*)d_in[5];
    const float* b_dst     = (const float*)d_in[6];
    const float* attn      = (const float*)d_in[7];
    const float* Wc1       = (const float*)d_in[8];
    const float* bc1       = (const float*)d_in[9];
    const float* Wc2       = (const float*)d_in[10];
    const float* bc2       = (const float*)d_in[11];
    const float* Wc3       = (const float*)d_in[12];
    const float* bc3       = (const float*)d_in[13];
    const int*   src       = (const int*)d_in[14];
    const int*   dst       = (const int*)d_in[15];
    const int*   graph_ids = (const int*)d_in[16];
    float* out = (float*)d_out;

    float *p_h, *p_fs, *p_fd;
    unsigned *p_ah_hi, *p_ah_lo, *p_af_hi, *p_af_lo;
    unsigned *p_win_hi, *p_win_lo, *p_ws_hi, *p_ws_lo, *p_wd_hi, *p_wd_lo;
    cudaGetSymbolAddress((void**)&p_h,  g_h);
    cudaGetSymbolAddress((void**)&p_fs, g_fs);
    cudaGetSymbolAddress((void**)&p_fd, g_fd);
    cudaGetSymbolAddress((void**)&p_ah_hi, g_ah_hi);
    cudaGetSymbolAddress((void**)&p_ah_lo, g_ah_lo);
    cudaGetSymbolAddress((void**)&p_af_hi, g_af_hi);
    cudaGetSymbolAddress((void**)&p_af_lo, g_af_lo);
    cudaGetSymbolAddress((void**)&p_win_hi, g_win_hi);
    cudaGetSymbolAddress((void**)&p_win_lo, g_win_lo);
    cudaGetSymbolAddress((void**)&p_ws_hi, g_ws_hi);
    cudaGetSymbolAddress((void**)&p_ws_lo, g_ws_lo);
    cudaGetSymbolAddress((void**)&p_wd_hi, g_wd_hi);
    cudaGetSymbolAddress((void**)&p_wd_lo, g_wd_lo);

    cudaFuncSetAttribute(gemm_bf16x3_kernel,
                         cudaFuncAttributeMaxDynamicSharedMemorySize, GSMEM);

    cudaStream_t s2;
    cudaStreamCreateWithFlags(&s2, cudaStreamNonBlocking);
    cudaEvent_t evA, evB;
    cudaEventCreateWithFlags(&evA, cudaEventDisableTiming);
    cudaEventCreateWithFlags(&evB, cudaEventDisableTiming);

    // main: pack everything (R14 arrangement)
    const int NPACK = NN * K2IN + WIN_P + 2 * LAYERS * WL_P;
    cudaEventRecord(evA, 0);
    pack_all_kernel<<<(NPACK + 255) / 256, 256>>>(W_in, W_src, W_dst, feature);

    // stream 2: CSR chain, overlapped with pack + GEMM1
    cudaStreamWaitEvent(s2, evA, 0);
    zero_cnt_kernel<<<(NN + 255) / 256, 256, 0, s2>>>();
    count_kernel<<<(NE + 255) / 256, 256, 0, s2>>>(dst);
    scan_kernel<<<1, 1024, 0, s2>>>();
    fill_kernel<<<(NE + 255) / 256, 256, 0, s2>>>(src, dst);
    gbound_kernel<<<1, 128, 0, s2>>>(graph_ids);
    cudaEventRecord(evB, s2);

    const int MROWS = (NN + GBM - 1) / GBM;
    const int NB = HID / GBN;
    dim3 grid1(NB, MROWS);
    dim3 grid2(2 * NB, MROWS);

    gemm_bf16x3_kernel<<<grid1, 256, GSMEM>>>(
        p_af_hi, p_af_lo, p_win_hi, p_win_lo, p_win_hi, p_win_lo,
        b_in, b_in, p_h, p_h, p_ah_hi, p_ah_lo,
        NN, K2IN, NB, 1);

    cudaStreamWaitEvent(0, evB, 0);

    const int fused_blocks = (NN + 1) / 2;   // 2 warps per block
    for (int l = 0; l < LAYERS; l++) {
        const float* bs = b_src + (size_t)l * HID;
        const float* bd = b_dst + (size_t)l * HID;
        const float* al = attn + (size_t)l * HEADS * DH;

        gemm_bf16x3_kernel<<<grid2, 256, GSMEM>>>(
            p_ah_hi, p_ah_lo,
            p_ws_hi + (size_t)l * WL_P, p_ws_lo + (size_t)l * WL_P,
            p_wd_hi + (size_t)l * WL_P, p_wd_lo + (size_t)l * WL_P,
            bs, bd, p_fs, p_fd, (unsigned*)0, (unsigned*)0,
            NN, K2L, NB, 0);

        fused_edge_kernel<<<fused_blocks, 64>>>(al, (l + 1 < LAYERS) ? 1 : 0);
    }

    poolfc_kernel<<<NG, 256>>>(Wc1, bc1, Wc2, bc2, Wc3, bc3, out);
}